// round 1
// baseline (speedup 1.0000x reference)
#include <cuda_runtime.h>

#define NCOL 65536
#define NB 32
#define NPTS 2048

#define OFF1 0
#define OFF2 64
#define OFF3 192
#define OFFH1 1216
#define OFFH2 1728
#define OFFH3 1984
#define NSTAT 2112

// ---- scratch (static device globals; no runtime allocation) ----
__device__ float d_raw1[64 * NCOL];     // conv1 out (pre-BN)
__device__ float d_raw2[128 * NCOL];    // conv2 out (pre-BN)
__device__ float d_rawh1[512 * NCOL];   // h1 out (pre-BN)
__device__ float d_rawh2[256 * NCOL];   // h2 out (pre-BN)
__device__ float d_rawh3[128 * NCOL];   // h3 out (pre-BN)
__device__ float d_sum[NSTAT];
__device__ float d_sq[NSTAT];
__device__ float d_scale[NSTAT];
__device__ float d_shift[NSTAT];
__device__ unsigned d_gmax[NB * 1024];  // encoded per-(b,c) max of conv3 raw out
__device__ float d_gbn[NB * 1024];      // BN(max)
__device__ float d_hvec[NB * 512];      // h_w1[:, :1024] @ g_bn + h_b1  (per-batch col bias)
__device__ int d_nv[NB];

// ---------------------------------------------------------------
__global__ void zero_kernel() {
    int i = blockIdx.x * 256 + threadIdx.x;
    if (i < NSTAT) { d_sum[i] = 0.f; d_sq[i] = 0.f; }
    if (i < NB * 1024) d_gmax[i] = 0u;
    if (i < NB) d_nv[i] = 0;
}

// conv1: 3 -> 64, K=3, dedicated kernel
__global__ void conv1_kernel(const float* __restrict__ pts,
                             const float* __restrict__ w,
                             const float* __restrict__ b) {
    __shared__ float ws[192];
    __shared__ float bs[64];
    int tid = threadIdx.x;
    if (tid < 192) ws[tid] = w[tid];
    if (tid < 64) bs[tid] = b[tid];
    __syncthreads();
    int col = blockIdx.x * 256 + tid;
    int bb = col >> 11, n = col & 2047;
    const float* p = pts + (size_t)bb * 3 * NPTS + n;
    float p0 = p[0], p1 = p[NPTS], p2 = p[2 * NPTS];
#pragma unroll
    for (int oc = 0; oc < 64; oc++) {
        float v = fmaf(ws[oc * 3], p0, fmaf(ws[oc * 3 + 1], p1, fmaf(ws[oc * 3 + 2], p2, bs[oc])));
        d_raw1[oc * NCOL + col] = v;
    }
}

// per-channel sum/sumsq over a stored raw tensor (used for conv1 only)
__global__ void stats_kernel(const float* __restrict__ raw, int off) {
    int c = blockIdx.x;
    const float* p = raw + (size_t)c * NCOL + blockIdx.y * 4096;
    float s = 0.f, q = 0.f;
    for (int i = threadIdx.x; i < 4096; i += 256) {
        float v = p[i];
        s += v;
        q = fmaf(v, v, q);
    }
#pragma unroll
    for (int o = 16; o >= 1; o >>= 1) {
        s += __shfl_xor_sync(0xffffffffu, s, o);
        q += __shfl_xor_sync(0xffffffffu, q, o);
    }
    __shared__ float ss[8], qq[8];
    int w = threadIdx.x >> 5, lane = threadIdx.x & 31;
    if (lane == 0) { ss[w] = s; qq[w] = q; }
    __syncthreads();
    if (threadIdx.x == 0) {
        float S = 0.f, Q = 0.f;
        for (int i = 0; i < 8; i++) { S += ss[i]; Q += qq[i]; }
        atomicAdd(&d_sum[off + c], S);
        atomicAdd(&d_sq[off + c], Q);
    }
}

__global__ void finalize_kernel(int C, int off,
                                const float* __restrict__ g,
                                const float* __restrict__ be) {
    int c = blockIdx.x * 128 + threadIdx.x;
    if (c >= C) return;
    float m = d_sum[off + c] * (1.0f / NCOL);
    float v = d_sq[off + c] * (1.0f / NCOL) - m * m;
    float sc = g[c] * rsqrtf(v + 1e-5f);
    d_scale[off + c] = sc;
    d_shift[off + c] = fmaf(-m, sc, be[c]);
}

// ---------------------------------------------------------------
// Generic GEMM:  Y[M x 65536] = W[M x K] @ act(Xraw) (+bias or per-batch colbias)
// act(v) = relu(scale[k]*v + shift[k])  -- previous layer's BN+relu fused into the load.
// Epilogue: optional store, always per-channel sum/sumsq atomics, optional per-(b,c) max.
template <bool STORE, bool DOMAX, bool COLBIAS>
__global__ void __launch_bounds__(256, 2) gemm_kernel(
    const float* __restrict__ W, int lda, int woff,
    const float* __restrict__ bias,
    const float* __restrict__ Xraw, int actoff,
    float* __restrict__ Y,
    int statoff, int Mtot, int K,
    const float* __restrict__ colbias) {
    __shared__ float As[8][132];
    __shared__ float Xs[8][132];
    const int tid = threadIdx.x;
    const int tx = tid & 15;
    const int ty = tid >> 4;
    const int col0 = blockIdx.x * 128;
    const int row0 = blockIdx.y * 128;
    float acc[8][8];
#pragma unroll
    for (int i = 0; i < 8; i++)
#pragma unroll
        for (int j = 0; j < 8; j++) acc[i][j] = 0.f;

    for (int k0 = 0; k0 < K; k0 += 8) {
#pragma unroll
        for (int l = 0; l < 4; l++) {
            int i = tid + l * 256;
            int m = i >> 3, kk = i & 7;
            As[kk][m] = W[(size_t)(row0 + m) * lda + (woff + k0 + kk)];
        }
#pragma unroll
        for (int l = 0; l < 4; l++) {
            int i = tid + l * 256;
            int kk = i >> 7, c = i & 127;
            float v = Xraw[(size_t)(k0 + kk) * NCOL + col0 + c];
            v = fmaxf(fmaf(d_scale[actoff + k0 + kk], v, d_shift[actoff + k0 + kk]), 0.f);
            Xs[kk][c] = v;
        }
        __syncthreads();
#pragma unroll
        for (int kk = 0; kk < 8; kk++) {
            float a[8], x[8];
#pragma unroll
            for (int i = 0; i < 4; i++) {
                a[i] = As[kk][ty * 4 + i];
                a[4 + i] = As[kk][64 + ty * 4 + i];
                x[i] = Xs[kk][tx * 4 + i];
                x[4 + i] = Xs[kk][64 + tx * 4 + i];
            }
#pragma unroll
            for (int i = 0; i < 8; i++)
#pragma unroll
                for (int j = 0; j < 8; j++) acc[i][j] = fmaf(a[i], x[j], acc[i][j]);
        }
        __syncthreads();
    }

    const int bb = col0 >> 11;  // 128-col tile lies within one batch (128 | 2048)

    // bias / per-batch column bias (before stats: part of the conv output)
#pragma unroll
    for (int i = 0; i < 8; i++) {
        int row = row0 + ((i < 4) ? (ty * 4 + i) : (64 + ty * 4 + (i - 4)));
        float badd;
        if (COLBIAS) badd = colbias[bb * Mtot + row];
        else badd = bias[row];
#pragma unroll
        for (int j = 0; j < 8; j++) acc[i][j] += badd;
    }

    if (STORE) {
#pragma unroll
        for (int i = 0; i < 8; i++) {
            int row = row0 + ((i < 4) ? (ty * 4 + i) : (64 + ty * 4 + (i - 4)));
            float4 v0 = make_float4(acc[i][0], acc[i][1], acc[i][2], acc[i][3]);
            float4 v1 = make_float4(acc[i][4], acc[i][5], acc[i][6], acc[i][7]);
            *(float4*)&Y[(size_t)row * NCOL + col0 + tx * 4] = v0;
            *(float4*)&Y[(size_t)row * NCOL + col0 + 64 + tx * 4] = v1;
        }
    }

    // per-row stats (and optional per-(b,row) max): reduce across the 16 tx lanes
#pragma unroll
    for (int i = 0; i < 8; i++) {
        float s = 0.f, q = 0.f, mx = -3.4e38f;
#pragma unroll
        for (int j = 0; j < 8; j++) {
            float v = acc[i][j];
            s += v;
            q = fmaf(v, v, q);
            if (DOMAX) mx = fmaxf(mx, v);
        }
#pragma unroll
        for (int o = 8; o >= 1; o >>= 1) {
            s += __shfl_xor_sync(0xffffffffu, s, o);
            q += __shfl_xor_sync(0xffffffffu, q, o);
            if (DOMAX) mx = fmaxf(mx, __shfl_xor_sync(0xffffffffu, mx, o));
        }
        if (tx == 0) {
            int row = row0 + ((i < 4) ? (ty * 4 + i) : (64 + ty * 4 + (i - 4)));
            atomicAdd(&d_sum[statoff + row], s);
            atomicAdd(&d_sq[statoff + row], q);
            if (DOMAX) {
                unsigned u = __float_as_uint(mx);
                u = (u >> 31) ? ~u : (u | 0x80000000u);
                atomicMax(&d_gmax[bb * Mtot + row], u);
            }
        }
    }
}

// decode max, apply conv3's BN affine -> g_bn
__global__ void gbn_kernel() {
    int i = blockIdx.x * 256 + threadIdx.x;  // 32 * 1024
    unsigned u = d_gmax[i];
    float f = (u >> 31) ? __uint_as_float(u & 0x7FFFFFFFu) : __uint_as_float(~u);
    int c = i & 1023;
    d_gbn[i] = fmaf(d_scale[OFF3 + c], f, d_shift[OFF3 + c]);
}

// hvec[b][oc] = h_w1[oc, :1024] @ g_bn[b] + h_b1[oc]
__global__ void hvec_kernel(const float* __restrict__ w1, const float* __restrict__ b1) {
    int bb = blockIdx.x;
    int oc = blockIdx.y * 128 + threadIdx.x;
    __shared__ float gb[1024];
    for (int i = threadIdx.x; i < 1024; i += 128) gb[i] = d_gbn[bb * 1024 + i];
    __syncthreads();
    float a = b1[oc];
    const float* wr = w1 + (size_t)oc * 1088;
#pragma unroll 4
    for (int k = 0; k < 1024; k++) a = fmaf(wr[k], gb[k], a);
    d_hvec[bb * 512 + oc] = a;
}

// h4 (128 -> 1), weights = 1 + y, write into d_out, count valid per batch
__global__ void h4_kernel(const float* __restrict__ w4, const float* __restrict__ b4,
                          float* __restrict__ out) {
    __shared__ float ws[128];
    int tid = threadIdx.x;
    if (tid < 128) ws[tid] = w4[tid];
    __syncthreads();
    int col = blockIdx.x * 256 + tid;
    float a = b4[0];
#pragma unroll 4
    for (int k = 0; k < 128; k++) {
        float v = d_rawh3[(size_t)k * NCOL + col];
        v = fmaxf(fmaf(d_scale[OFFH3 + k], v, d_shift[OFFH3 + k]), 0.f);
        a = fmaf(ws[k], v, a);
    }
    float wv = 1.f + a;
    out[96 + col] = wv;
    int valid = (wv > 1e-4f) ? 1 : 0;
#pragma unroll
    for (int o = 16; o >= 1; o >>= 1) valid += __shfl_xor_sync(0xffffffffu, valid, o);
    __shared__ int vs[8];
    if ((tid & 31) == 0) vs[tid >> 5] = valid;
    __syncthreads();
    if (tid == 0) {
        int s = 0;
        for (int i = 0; i < 8; i++) s += vs[i];
        atomicAdd(&d_nv[(blockIdx.x * 256) >> 11], s);
    }
}

// per-batch weighted 3x3 normal equations + Cholesky solve
__global__ void solve_kernel(const float* __restrict__ pts, float* __restrict__ out) {
    int bb = blockIdx.x;
    const float* w = out + 96 + bb * NPTS;
    const float* px = pts + (size_t)bb * 3 * NPTS;
    bool usew = d_nv[bb] > 3;
    float acc[9];
#pragma unroll
    for (int k = 0; k < 9; k++) acc[k] = 0.f;
    for (int n = threadIdx.x; n < NPTS; n += 256) {
        float wv = w[n];
        float we = usew ? ((wv > 1e-4f) ? wv : 0.f) : 1.f;
        float x = px[n], y = px[NPTS + n], z = px[2 * NPTS + n];
        acc[0] = fmaf(we * x, x, acc[0]);
        acc[1] = fmaf(we * x, y, acc[1]);
        acc[2] += we * x;
        acc[3] = fmaf(we * y, y, acc[3]);
        acc[4] += we * y;
        acc[5] += we;
        acc[6] = fmaf(we * x, z, acc[6]);
        acc[7] = fmaf(we * y, z, acc[7]);
        acc[8] = fmaf(we, z, acc[8]);
    }
#pragma unroll
    for (int k = 0; k < 9; k++)
#pragma unroll
        for (int o = 16; o >= 1; o >>= 1) acc[k] += __shfl_xor_sync(0xffffffffu, acc[k], o);
    __shared__ float red[8][9];
    int wid = threadIdx.x >> 5, lane = threadIdx.x & 31;
    if (lane == 0)
        for (int k = 0; k < 9; k++) red[wid][k] = acc[k];
    __syncthreads();
    if (threadIdx.x == 0) {
        float a[9];
        for (int k = 0; k < 9; k++) {
            float s = 0.f;
            for (int i = 0; i < 8; i++) s += red[i][k];
            a[k] = s;
        }
        float a11 = a[0], a12 = a[1], a13 = a[2], a22 = a[3], a23 = a[4], a33 = a[5];
        float b1 = a[6], b2 = a[7], b3 = a[8];
        float L11 = sqrtf(a11);
        float L21 = a12 / L11, L31 = a13 / L11;
        float L22 = sqrtf(a22 - L21 * L21);
        float L32 = (a23 - L31 * L21) / L22;
        float L33 = sqrtf(a33 - L31 * L31 - L32 * L32);
        float y1 = b1 / L11;
        float y2 = (b2 - L21 * y1) / L22;
        float y3 = (b3 - L31 * y1 - L32 * y2) / L33;
        float be3 = y3 / L33;
        float be2 = (y2 - L32 * be3) / L22;
        float be1 = (y1 - L21 * be2 - L31 * be3) / L11;
        out[bb * 3 + 0] = be1;
        out[bb * 3 + 1] = be2;
        out[bb * 3 + 2] = be3;
    }
}

// ---------------------------------------------------------------
extern "C" void kernel_launch(void* const* d_in, const int* in_sizes, int n_in,
                              void* d_out, int out_size) {
    const float* pts = (const float*)d_in[0];
    const float* e_w1 = (const float*)d_in[1];
    const float* e_b1 = (const float*)d_in[2];
    const float* e_g1 = (const float*)d_in[3];
    const float* e_be1 = (const float*)d_in[4];
    const float* e_w2 = (const float*)d_in[5];
    const float* e_b2 = (const float*)d_in[6];
    const float* e_g2 = (const float*)d_in[7];
    const float* e_be2 = (const float*)d_in[8];
    const float* e_w3 = (const float*)d_in[9];
    const float* e_b3 = (const float*)d_in[10];
    const float* e_g3 = (const float*)d_in[11];
    const float* e_be3 = (const float*)d_in[12];
    const float* h_w1 = (const float*)d_in[13];
    const float* h_b1 = (const float*)d_in[14];
    const float* h_g1 = (const float*)d_in[15];
    const float* h_be1 = (const float*)d_in[16];
    const float* h_w2 = (const float*)d_in[17];
    const float* h_b2 = (const float*)d_in[18];
    const float* h_g2 = (const float*)d_in[19];
    const float* h_be2 = (const float*)d_in[20];
    const float* h_w3 = (const float*)d_in[21];
    const float* h_b3 = (const float*)d_in[22];
    const float* h_g3 = (const float*)d_in[23];
    const float* h_be3 = (const float*)d_in[24];
    const float* h_w4 = (const float*)d_in[25];
    const float* h_b4 = (const float*)d_in[26];
    float* out = (float*)d_out;

    float *p_raw1, *p_raw2, *p_rawh1, *p_rawh2, *p_rawh3, *p_hvec;
    cudaGetSymbolAddress((void**)&p_raw1, d_raw1);
    cudaGetSymbolAddress((void**)&p_raw2, d_raw2);
    cudaGetSymbolAddress((void**)&p_rawh1, d_rawh1);
    cudaGetSymbolAddress((void**)&p_rawh2, d_rawh2);
    cudaGetSymbolAddress((void**)&p_rawh3, d_rawh3);
    cudaGetSymbolAddress((void**)&p_hvec, d_hvec);

    zero_kernel<<<128, 256>>>();
    conv1_kernel<<<256, 256>>>(pts, e_w1, e_b1);
    stats_kernel<<<dim3(64, 16), 256>>>(p_raw1, OFF1);
    finalize_kernel<<<1, 128>>>(64, OFF1, e_g1, e_be1);
    // conv2: 128 x 65536 x 64
    gemm_kernel<true, false, false><<<dim3(512, 1), 256>>>(e_w2, 64, 0, e_b2, p_raw1, OFF1,
                                                           p_raw2, OFF2, 128, 64, nullptr);
    finalize_kernel<<<1, 128>>>(128, OFF2, e_g2, e_be2);
    // conv3: 1024 x 65536 x 128  (no store; stats + max only)
    gemm_kernel<false, true, false><<<dim3(512, 8), 256>>>(e_w3, 128, 0, e_b3, p_raw2, OFF2,
                                                           nullptr, OFF3, 1024, 128, nullptr);
    finalize_kernel<<<8, 128>>>(1024, OFF3, e_g3, e_be3);
    gbn_kernel<<<128, 256>>>();
    hvec_kernel<<<dim3(32, 4), 128>>>(h_w1, h_b1);
    // h1 (pointfeat part): 512 x 65536 x 64, per-batch column bias = hvec
    gemm_kernel<true, false, true><<<dim3(512, 4), 256>>>(h_w1, 1088, 1024, h_b1, p_raw1, OFF1,
                                                          p_rawh1, OFFH1, 512, 64, p_hvec);
    finalize_kernel<<<4, 128>>>(512, OFFH1, h_g1, h_be1);
    // h2: 256 x 65536 x 512
    gemm_kernel<true, false, false><<<dim3(512, 2), 256>>>(h_w2, 512, 0, h_b2, p_rawh1, OFFH1,
                                                           p_rawh2, OFFH2, 256, 512, nullptr);
    finalize_kernel<<<2, 128>>>(256, OFFH2, h_g2, h_be2);
    // h3: 128 x 65536 x 256
    gemm_kernel<true, false, false><<<dim3(512, 1), 256>>>(h_w3, 256, 0, h_b3, p_rawh2, OFFH2,
                                                           p_rawh3, OFFH3, 128, 256, nullptr);
    finalize_kernel<<<1, 128>>>(128, OFFH3, h_g3, h_be3);
    h4_kernel<<<256, 256>>>(h_w4, h_b4, out);
    solve_kernel<<<32, 256>>>(pts, out);
}